// round 9
// baseline (speedup 1.0000x reference)
#include <cuda_runtime.h>
#include <cuda_bf16.h>
#include <math.h>

#define Bdim 64
#define Sdim 1024
#define Idim 1024
#define Hdim 1024
#define NB_REC 128
#define REC_THREADS 512
#define PCH 1032  // bf16 smem row pitch: P%64==8 -> frag LDS banks (4r+tg)%32

// Scratch (allocation-free rule: __device__ globals)
__device__ unsigned g_cnt;
__device__ unsigned g_flag;
// bf16 hi/lo split operands for tensor-core wx GEMM
__device__ __nv_bfloat16 g_Xhi[(size_t)Bdim * Sdim * Idim];
__device__ __nv_bfloat16 g_Xlo[(size_t)Bdim * Sdim * Idim];
__device__ __nv_bfloat16 g_Whi[Hdim * Idim];
__device__ __nv_bfloat16 g_Wlo[Hdim * Idim];
// bf16 hi/lo split of Whh (recurrent weights) and double-buffered h state
__device__ __nv_bfloat16 g_Hhhi[Hdim * Hdim];
__device__ __nv_bfloat16 g_Hhlo[Hdim * Hdim];
__device__ __nv_bfloat16 g_hbh[2][Bdim * Hdim];
__device__ __nv_bfloat16 g_hbl[2][Bdim * Hdim];

typedef unsigned long long ull;

// ---------------------------------------------------------------------------
__device__ __forceinline__ void fma2(ull& c, ull a, ull b) {
    asm("fma.rn.f32x2 %0, %1, %2, %0;" : "+l"(c) : "l"(a), "l"(b));
}
__device__ __forceinline__ float f2sum(ull v) {
    float2 f = *reinterpret_cast<float2*>(&v);
    return f.x + f.y;
}
__device__ __forceinline__ void cp16(void* d, const void* s) {
    unsigned sd = (unsigned)__cvta_generic_to_shared(d);
    asm volatile("cp.async.cg.shared.global [%0], [%1], 16;" :: "r"(sd), "l"(s));
}
#define CP_COMMIT() asm volatile("cp.async.commit_group;")
#define CP_WAIT(n) asm volatile("cp.async.wait_group %0;" :: "n"(n))

__device__ __forceinline__ void bulk_g2s(unsigned dst, const void* src,
                                         unsigned bytes, unsigned mbar) {
    asm volatile(
        "cp.async.bulk.shared::cluster.global.mbarrier::complete_tx::bytes "
        "[%0], [%1], %2, [%3];"
        :: "r"(dst), "l"(src), "r"(bytes), "r"(mbar) : "memory");
}
__device__ __forceinline__ void mbar_init(unsigned mbar, unsigned cnt) {
    asm volatile("mbarrier.init.shared.b64 [%0], %1;" :: "r"(mbar), "r"(cnt)
                 : "memory");
}
__device__ __forceinline__ void mbar_expect_tx(unsigned mbar, unsigned tx) {
    asm volatile("mbarrier.arrive.expect_tx.shared.b64 _, [%0], %1;"
                 :: "r"(mbar), "r"(tx) : "memory");
}
__device__ __forceinline__ void mbar_wait(unsigned mbar, unsigned parity) {
    asm volatile(
        "{\n\t"
        ".reg .pred P1;\n\t"
        "WAIT_LOOP_%=:\n\t"
        "mbarrier.try_wait.parity.acquire.cta.shared::cta.b64 P1, [%0], %1, 0x989680;\n\t"
        "@P1 bra.uni WAIT_DONE_%=;\n\t"
        "bra.uni WAIT_LOOP_%=;\n\t"
        "WAIT_DONE_%=:\n\t"
        "}"
        :: "r"(mbar), "r"(parity) : "memory");
}
__device__ __forceinline__ unsigned atom_add_release(unsigned* p, unsigned v) {
    unsigned old;
    asm volatile("atom.add.release.gpu.u32 %0, [%1], %2;"
                 : "=r"(old) : "l"(p), "r"(v) : "memory");
    return old;
}
__device__ __forceinline__ void st_release(unsigned* p, unsigned v) {
    asm volatile("st.release.gpu.u32 [%0], %1;" :: "l"(p), "r"(v) : "memory");
}
__device__ __forceinline__ unsigned ld_acquire(const unsigned* p) {
    unsigned v;
    asm volatile("ld.acquire.gpu.u32 %0, [%1];" : "=r"(v) : "l"(p) : "memory");
    return v;
}
// bf16 mma: D(16x8,f32) += A(16x16,row) * B(16x8,col)
__device__ __forceinline__ void mma_bf16(float* c, const unsigned* a,
                                         const unsigned* b) {
    asm volatile(
        "mma.sync.aligned.m16n8k16.row.col.f32.bf16.bf16.f32 "
        "{%0,%1,%2,%3}, {%4,%5,%6,%7}, {%8,%9}, {%0,%1,%2,%3};"
        : "+f"(c[0]), "+f"(c[1]), "+f"(c[2]), "+f"(c[3])
        : "r"(a[0]), "r"(a[1]), "r"(a[2]), "r"(a[3]), "r"(b[0]), "r"(b[1]));
}

// ---------------------------------------------------------------------------
__global__ void reset_state() {
    if (threadIdx.x == 0) {
        g_cnt = 0;
        g_flag = 0;
    }
}

// h0 fp32 -> bf16 hi/lo into buffer 0
__global__ void copy_h(const float* __restrict__ hin) {
    int i = blockIdx.x * blockDim.x + threadIdx.x;
    for (; i < Bdim * Hdim; i += gridDim.x * blockDim.x) {
        float v = hin[i];
        __nv_bfloat16 h = __float2bfloat16(v);
        g_hbh[0][i] = h;
        g_hbl[0][i] = __float2bfloat16(v - __bfloat162float(h));
    }
}

// split fp32 -> bf16 hi + bf16 lo (lo = round(v - hi))
__global__ void split_x(const float* __restrict__ src) {
    size_t i = (size_t)(blockIdx.x * blockDim.x + threadIdx.x) * 4;
    const size_t n = (size_t)Bdim * Sdim * Idim;
    for (; i < n; i += (size_t)gridDim.x * blockDim.x * 4) {
        float4 v = *reinterpret_cast<const float4*>(src + i);
        __nv_bfloat16 h0 = __float2bfloat16(v.x), h1 = __float2bfloat16(v.y);
        __nv_bfloat16 h2 = __float2bfloat16(v.z), h3 = __float2bfloat16(v.w);
        __nv_bfloat162 hi01{h0, h1}, hi23{h2, h3};
        __nv_bfloat162 lo01{__float2bfloat16(v.x - __bfloat162float(h0)),
                            __float2bfloat16(v.y - __bfloat162float(h1))};
        __nv_bfloat162 lo23{__float2bfloat16(v.z - __bfloat162float(h2)),
                            __float2bfloat16(v.w - __bfloat162float(h3))};
        *reinterpret_cast<__nv_bfloat162*>(&g_Xhi[i]) = hi01;
        *reinterpret_cast<__nv_bfloat162*>(&g_Xhi[i + 2]) = hi23;
        *reinterpret_cast<__nv_bfloat162*>(&g_Xlo[i]) = lo01;
        *reinterpret_cast<__nv_bfloat162*>(&g_Xlo[i + 2]) = lo23;
    }
}

__global__ void split_w(const float* __restrict__ src) {
    int i = blockIdx.x * blockDim.x + threadIdx.x;
    for (; i < Hdim * Idim; i += gridDim.x * blockDim.x) {
        float v = src[i];
        __nv_bfloat16 h = __float2bfloat16(v);
        g_Whi[i] = h;
        g_Wlo[i] = __float2bfloat16(v - __bfloat162float(h));
    }
}

__global__ void split_whh(const float* __restrict__ src) {
    int i = blockIdx.x * blockDim.x + threadIdx.x;
    for (; i < Hdim * Hdim; i += gridDim.x * blockDim.x) {
        float v = src[i];
        __nv_bfloat16 h = __float2bfloat16(v);
        g_Hhhi[i] = h;
        g_Hhlo[i] = __float2bfloat16(v - __bfloat162float(h));
    }
}

// ---------------------------------------------------------------------------
// Phase 1: wx = X @ Wih^T + b via bf16 tensor cores (unchanged from R8).
// ---------------------------------------------------------------------------
__global__ __launch_bounds__(256) void wx_gemm_tc(const float* __restrict__ bias,
                                                  float* __restrict__ out) {
    extern __shared__ __nv_bfloat16 smem_bf[];
    __nv_bfloat16* Ah = smem_bf;           // 2 bufs x 128 x 40
    __nv_bfloat16* Al = smem_bf + 10240;
    __nv_bfloat16* Bh = smem_bf + 20480;   // 2 bufs x 64 x 40
    __nv_bfloat16* Bl = smem_bf + 25600;

    const int tid = threadIdx.x;
    const int wid = tid >> 5, lane = tid & 31;
    const int g = lane >> 2, tg = lane & 3;
    const int warpM = (wid & 3) * 32;
    const int warpN = (wid >> 2) * 32;
    const long mBase = (long)blockIdx.y * 128;
    const int nBase = blockIdx.x * 64;

    const __nv_bfloat16* xh = g_Xhi + mBase * Idim;
    const __nv_bfloat16* xl = g_Xlo + mBase * Idim;
    const __nv_bfloat16* wh = g_Whi + (size_t)nBase * Idim;
    const __nv_bfloat16* wl = g_Wlo + (size_t)nBase * Idim;

    float acc[2][4][4];
#pragma unroll
    for (int i = 0; i < 2; i++)
#pragma unroll
        for (int j = 0; j < 4; j++)
#pragma unroll
            for (int r = 0; r < 4; r++) acc[i][j][r] = 0.f;

    const int ar0 = tid >> 2, aoff0 = (tid & 3) * 8;
    const int ar1 = (tid + 256) >> 2, aoff1 = ((tid + 256) & 3) * 8;
    const int br = tid >> 2, boff = (tid & 3) * 8;

#define LOAD_CHUNK(B, K0)                                                      \
    do {                                                                       \
        cp16(&Ah[(B) * 5120 + ar0 * 40 + aoff0], xh + ar0 * Idim + (K0) + aoff0); \
        cp16(&Ah[(B) * 5120 + ar1 * 40 + aoff1], xh + ar1 * Idim + (K0) + aoff1); \
        cp16(&Al[(B) * 5120 + ar0 * 40 + aoff0], xl + ar0 * Idim + (K0) + aoff0); \
        cp16(&Al[(B) * 5120 + ar1 * 40 + aoff1], xl + ar1 * Idim + (K0) + aoff1); \
        cp16(&Bh[(B) * 2560 + br * 40 + boff], wh + br * Idim + (K0) + boff);  \
        cp16(&Bl[(B) * 2560 + br * 40 + boff], wl + br * Idim + (K0) + boff);  \
    } while (0)

    LOAD_CHUNK(0, 0);
    CP_COMMIT();

    int buf = 0;
    for (int kt = 0; kt < Idim / 32; kt++) {
        if (kt + 1 < Idim / 32) LOAD_CHUNK(buf ^ 1, (kt + 1) * 32);
        CP_COMMIT();
        CP_WAIT(1);
        __syncthreads();

        const __nv_bfloat16* ah = Ah + buf * 5120;
        const __nv_bfloat16* al = Al + buf * 5120;
        const __nv_bfloat16* bh = Bh + buf * 2560;
        const __nv_bfloat16* bl = Bl + buf * 2560;

#pragma unroll
        for (int kk = 0; kk < 32; kk += 16) {
            unsigned afh[2][4], afl[2][4], bfh[4][2], bfl[4][2];
#pragma unroll
            for (int i = 0; i < 2; i++) {
                int r0 = (warpM + i * 16 + g) * 40 + kk + tg * 2;
                int r1 = r0 + 8 * 40;
                afh[i][0] = *reinterpret_cast<const unsigned*>(&ah[r0]);
                afh[i][1] = *reinterpret_cast<const unsigned*>(&ah[r1]);
                afh[i][2] = *reinterpret_cast<const unsigned*>(&ah[r0 + 8]);
                afh[i][3] = *reinterpret_cast<const unsigned*>(&ah[r1 + 8]);
                afl[i][0] = *reinterpret_cast<const unsigned*>(&al[r0]);
                afl[i][1] = *reinterpret_cast<const unsigned*>(&al[r1]);
                afl[i][2] = *reinterpret_cast<const unsigned*>(&al[r0 + 8]);
                afl[i][3] = *reinterpret_cast<const unsigned*>(&al[r1 + 8]);
            }
#pragma unroll
            for (int j = 0; j < 4; j++) {
                int r0 = (warpN + j * 8 + g) * 40 + kk + tg * 2;
                bfh[j][0] = *reinterpret_cast<const unsigned*>(&bh[r0]);
                bfh[j][1] = *reinterpret_cast<const unsigned*>(&bh[r0 + 8]);
                bfl[j][0] = *reinterpret_cast<const unsigned*>(&bl[r0]);
                bfl[j][1] = *reinterpret_cast<const unsigned*>(&bl[r0 + 8]);
            }
#pragma unroll
            for (int i = 0; i < 2; i++)
#pragma unroll
                for (int j = 0; j < 4; j++) {
                    mma_bf16(acc[i][j], afh[i], bfh[j]);
                    mma_bf16(acc[i][j], afh[i], bfl[j]);
                    mma_bf16(acc[i][j], afl[i], bfh[j]);
                }
        }
        __syncthreads();
        buf ^= 1;
    }

#pragma unroll
    for (int i = 0; i < 2; i++) {
        long row = mBase + warpM + i * 16 + g;
#pragma unroll
        for (int j = 0; j < 4; j++) {
            int col = nBase + warpN + j * 8 + tg * 2;
            float b0 = bias[col], b1 = bias[col + 1];
            float2 v0{acc[i][j][0] + b0, acc[i][j][1] + b1};
            float2 v1{acc[i][j][2] + b0, acc[i][j][3] + b1};
            *reinterpret_cast<float2*>(&out[row * Hdim + col]) = v0;
            *reinterpret_cast<float2*>(&out[(row + 8) * Hdim + col]) = v1;
        }
    }
}

// ---------------------------------------------------------------------------
// Phase 2: persistent recurrence, tensor-core compute.
// 128 CTAs x 512 threads. CTA = 32 cols x 16 batches.
// Whh bf16 hi/lo slice (32x1024, pitch 1032) resident in smem all steps.
// h published each step as bf16 hi/lo; staged via 32x cp.async.bulk (2KB).
// 16 warps = K-slices of 64: per warp 4x k16 iters, M16 x N32, 12 HMMA each
// (3-product split). Partials reduced via sRed overlay; fp32 wx/y/h state.
// ---------------------------------------------------------------------------
__global__ __launch_bounds__(REC_THREADS, 1)
void rnn_recur(const float* __restrict__ bhh, float* __restrict__ y,
               float* __restrict__ hlast) {
    extern __shared__ char smem_raw[];
    __nv_bfloat16* sWhi = reinterpret_cast<__nv_bfloat16*>(smem_raw);
    __nv_bfloat16* sWlo = reinterpret_cast<__nv_bfloat16*>(smem_raw + 66048);
    __nv_bfloat16* sHhi = reinterpret_cast<__nv_bfloat16*>(smem_raw + 132096);
    __nv_bfloat16* sHlo = reinterpret_cast<__nv_bfloat16*>(smem_raw + 165120);
    float* sRed = reinterpret_cast<float*>(smem_raw + 132096);  // overlay on sH
    __shared__ unsigned long long mbar_storage;

    const int tid = threadIdx.x;
    const int bid = blockIdx.x;
    const int colBase = (bid & 31) * 32;
    const int batchBase = (bid >> 5) * 16;
    const unsigned mbar = (unsigned)__cvta_generic_to_shared(&mbar_storage);
    const unsigned sHhi_a = (unsigned)__cvta_generic_to_shared(sHhi);
    const unsigned sHlo_a = (unsigned)__cvta_generic_to_shared(sHlo);

    if (tid == 0) mbar_init(mbar, 1);

    // cache Whh hi/lo slice: 32 rows x 1024 bf16 = 4096 chunks of 16B each
#pragma unroll
    for (int i = 0; i < 8; i++) {
        int chunk = tid + i * REC_THREADS;
        int r = chunk >> 7, c = chunk & 127;
        *reinterpret_cast<float4*>(
            reinterpret_cast<char*>(sWhi) + r * 2064 + c * 16) =
            *reinterpret_cast<const float4*>(
                reinterpret_cast<const char*>(&g_Hhhi[(size_t)(colBase + r) << 10]) +
                c * 16);
        *reinterpret_cast<float4*>(
            reinterpret_cast<char*>(sWlo) + r * 2064 + c * 16) =
            *reinterpret_cast<const float4*>(
                reinterpret_cast<const char*>(&g_Hhlo[(size_t)(colBase + r) << 10]) +
                c * 16);
    }
    __syncthreads();  // mbar init + sW visible

    const int wid = tid >> 5, lane = tid & 31;
    const int g = lane >> 2, tg = lane & 3;
    const int kBase = wid * 64;

    const int ob = tid >> 5;  // batch 0..15
    const int oc = tid & 31;  // col 0..31
    const float bv = bhh[colBase + oc];
    const long ybase = (((long)(batchBase + ob)) << 20) + colBase + oc;
    const int hoff = ((batchBase + ob) << 10) + colBase + oc;
    const int rbase = ob * 40 + oc;
    float hv = 0.f;

    for (int s = 0; s < Sdim; s++) {
        const int p = s & 1;
        // stage h hi/lo: 32 bulk copies of one 2KB row each (tx = 64KB)
        if (tid == 0) {
            asm volatile("fence.proxy.async.shared::cta;" ::: "memory");
            mbar_expect_tx(mbar, 32 * 2048);
            const __nv_bfloat16* hh = g_hbh[p] + ((long)batchBase << 10);
            const __nv_bfloat16* hl = g_hbl[p] + ((long)batchBase << 10);
#pragma unroll
            for (int r = 0; r < 16; r++) {
                bulk_g2s(sHhi_a + (unsigned)(r * 2064), hh + (r << 10), 2048, mbar);
                bulk_g2s(sHlo_a + (unsigned)(r * 2064), hl + (r << 10), 2048, mbar);
            }
        }
        float wxv = __ldg(&y[ybase + ((long)s << 10)]);  // overlap with copy
        mbar_wait(mbar, (unsigned)p);

        float acc[4][4];
#pragma unroll
        for (int j = 0; j < 4; j++)
#pragma unroll
            for (int r = 0; r < 4; r++) acc[j][r] = 0.f;

#pragma unroll
        for (int t = 0; t < 4; t++) {
            const int k = kBase + t * 16;
            unsigned ah[4], al[4];
            const int a0 = g * PCH + k + tg * 2;
            ah[0] = *reinterpret_cast<const unsigned*>(&sHhi[a0]);
            ah[1] = *reinterpret_cast<const unsigned*>(&sHhi[a0 + 8 * PCH]);
            ah[2] = *reinterpret_cast<const unsigned*>(&sHhi[a0 + 8]);
            ah[3] = *reinterpret_cast<const unsigned*>(&sHhi[a0 + 8 * PCH + 8]);
            al[0] = *reinterpret_cast<const unsigned*>(&sHlo[a0]);
            al[1] = *reinterpret_cast<const unsigned*>(&sHlo[a0 + 8 * PCH]);
            al[2] = *reinterpret_cast<const unsigned*>(&sHlo[a0 + 8]);
            al[3] = *reinterpret_cast<const unsigned*>(&sHlo[a0 + 8 * PCH + 8]);
#pragma unroll
            for (int j = 0; j < 4; j++) {
                const int b0 = (8 * j + g) * PCH + k + tg * 2;
                unsigned bh[2], bl[2];
                bh[0] = *reinterpret_cast<const unsigned*>(&sWhi[b0]);
                bh[1] = *reinterpret_cast<const unsigned*>(&sWhi[b0 + 8]);
                bl[0] = *reinterpret_cast<const unsigned*>(&sWlo[b0]);
                bl[1] = *reinterpret_cast<const unsigned*>(&sWlo[b0 + 8]);
                mma_bf16(acc[j], ah, bh);
                mma_bf16(acc[j], ah, bl);
                mma_bf16(acc[j], al, bh);
            }
        }
        __syncthreads();  // all sH reads done before sRed overlay writes

        // c0,c1 = (batch g, cols j*8+2tg..+1); c2,c3 = batch g+8
#pragma unroll
        for (int j = 0; j < 4; j++) {
            float2 v0{acc[j][0], acc[j][1]};
            float2 v1{acc[j][2], acc[j][3]};
            *reinterpret_cast<float2*>(
                &sRed[wid * 640 + g * 40 + j * 8 + tg * 2]) = v0;
            *reinterpret_cast<float2*>(
                &sRed[wid * 640 + (g + 8) * 40 + j * 8 + tg * 2]) = v1;
        }
        __syncthreads();

        float sum = 0.f;
#pragma unroll
        for (int w = 0; w < 16; w++) sum += sRed[w * 640 + rbase];

        hv = tanhf(wxv + sum + bv);
        __nv_bfloat16 hvh = __float2bfloat16(hv);
        g_hbh[1 - p][hoff] = hvh;
        g_hbl[1 - p][hoff] = __float2bfloat16(hv - __bfloat162float(hvh));
        y[ybase + ((long)s << 10)] = hv;
        __syncthreads();  // CTA writes done before release
        if (tid == 0) {
            unsigned arrived = atom_add_release(&g_cnt, 1u) + 1u;
            unsigned step = (unsigned)(s + 1);
            if (arrived == step * (unsigned)NB_REC) st_release(&g_flag, step);
            while (ld_acquire(&g_flag) < step) {
            }
        }
        __syncthreads();
    }

    hlast[hoff] = hv;
}

// ---------------------------------------------------------------------------
extern "C" void kernel_launch(void* const* d_in, const int* in_sizes, int n_in,
                              void* d_out, int out_size) {
    const float* x = (const float*)d_in[0];      // [B,S,I]
    const float* h0 = (const float*)d_in[1];     // [B,H]
    const float* Wih_w = (const float*)d_in[2];  // [H,I]
    const float* Wih_b = (const float*)d_in[3];  // [H]
    const float* Whh_w = (const float*)d_in[4];  // [H,H]
    const float* Whh_b = (const float*)d_in[5];  // [H]
    float* y = (float*)d_out;                       // [B,S,H]
    float* hlast = y + (size_t)Bdim * Sdim * Hdim;  // [B,H]

    const int rec_smem = 198144;  // W hi/lo 132KB + h hi/lo 66KB
    cudaFuncSetAttribute(rnn_recur, cudaFuncAttributeMaxDynamicSharedMemorySize,
                         rec_smem);
    const int gemm_smem = 30720 * 2;  // 61440
    cudaFuncSetAttribute(wx_gemm_tc, cudaFuncAttributeMaxDynamicSharedMemorySize,
                         gemm_smem);

    reset_state<<<1, 32>>>();
    copy_h<<<64, 256>>>(h0);
    split_x<<<1024, 256>>>(x);
    split_w<<<256, 256>>>(Wih_w);
    split_whh<<<256, 256>>>(Whh_w);
    wx_gemm_tc<<<dim3(Hdim / 64, (Bdim * Sdim) / 128), 256, gemm_smem>>>(Wih_b, y);
    rnn_recur<<<NB_REC, REC_THREADS, rec_smem>>>(Whh_b, y, hlast);
}

// round 10
// speedup vs baseline: 1.3868x; 1.3868x over previous
#include <cuda_runtime.h>
#include <cuda_bf16.h>
#include <math.h>

#define Bdim 64
#define Sdim 1024
#define Idim 1024
#define Hdim 1024
#define NB_REC 128
#define REC_THREADS 512
#define PCH 1032  // bf16 smem row pitch: B-frag LDS banks (4g+tg)%32 distinct

// Scratch (allocation-free rule: __device__ globals)
__device__ float g_hbuf[2][Bdim * Hdim];  // fp32 h state, double-buffered
__device__ unsigned g_cnt;
__device__ unsigned g_flag;
// bf16 hi/lo split operands for tensor-core GEMMs
__device__ __nv_bfloat16 g_Xhi[(size_t)Bdim * Sdim * Idim];
__device__ __nv_bfloat16 g_Xlo[(size_t)Bdim * Sdim * Idim];
__device__ __nv_bfloat16 g_Whi[Hdim * Idim];
__device__ __nv_bfloat16 g_Wlo[Hdim * Idim];
__device__ __nv_bfloat16 g_Hhhi[Hdim * Hdim];
__device__ __nv_bfloat16 g_Hhlo[Hdim * Hdim];

typedef unsigned long long ull;

// ---------------------------------------------------------------------------
__device__ __forceinline__ void cp16(void* d, const void* s) {
    unsigned sd = (unsigned)__cvta_generic_to_shared(d);
    asm volatile("cp.async.cg.shared.global [%0], [%1], 16;" :: "r"(sd), "l"(s));
}
#define CP_COMMIT() asm volatile("cp.async.commit_group;")
#define CP_WAIT(n) asm volatile("cp.async.wait_group %0;" :: "n"(n))

__device__ __forceinline__ void bulk_g2s(unsigned dst, const void* src,
                                         unsigned bytes, unsigned mbar) {
    asm volatile(
        "cp.async.bulk.shared::cluster.global.mbarrier::complete_tx::bytes "
        "[%0], [%1], %2, [%3];"
        :: "r"(dst), "l"(src), "r"(bytes), "r"(mbar) : "memory");
}
__device__ __forceinline__ void mbar_init(unsigned mbar, unsigned cnt) {
    asm volatile("mbarrier.init.shared.b64 [%0], %1;" :: "r"(mbar), "r"(cnt)
                 : "memory");
}
__device__ __forceinline__ void mbar_expect_tx(unsigned mbar, unsigned tx) {
    asm volatile("mbarrier.arrive.expect_tx.shared.b64 _, [%0], %1;"
                 :: "r"(mbar), "r"(tx) : "memory");
}
__device__ __forceinline__ void mbar_wait(unsigned mbar, unsigned parity) {
    asm volatile(
        "{\n\t"
        ".reg .pred P1;\n\t"
        "WAIT_LOOP_%=:\n\t"
        "mbarrier.try_wait.parity.acquire.cta.shared::cta.b64 P1, [%0], %1, 0x989680;\n\t"
        "@P1 bra.uni WAIT_DONE_%=;\n\t"
        "bra.uni WAIT_LOOP_%=;\n\t"
        "WAIT_DONE_%=:\n\t"
        "}"
        :: "r"(mbar), "r"(parity) : "memory");
}
__device__ __forceinline__ unsigned atom_add_release(unsigned* p, unsigned v) {
    unsigned old;
    asm volatile("atom.add.release.gpu.u32 %0, [%1], %2;"
                 : "=r"(old) : "l"(p), "r"(v) : "memory");
    return old;
}
__device__ __forceinline__ void st_release(unsigned* p, unsigned v) {
    asm volatile("st.release.gpu.u32 [%0], %1;" :: "l"(p), "r"(v) : "memory");
}
__device__ __forceinline__ unsigned ld_acquire(const unsigned* p) {
    unsigned v;
    asm volatile("ld.acquire.gpu.u32 %0, [%1];" : "=r"(v) : "l"(p) : "memory");
    return v;
}
// bf16 mma: D(16x8,f32) += A(16x16,row) * B(16x8,col)
__device__ __forceinline__ void mma_bf16(float* c, const unsigned* a,
                                         const unsigned* b) {
    asm volatile(
        "mma.sync.aligned.m16n8k16.row.col.f32.bf16.bf16.f32 "
        "{%0,%1,%2,%3}, {%4,%5,%6,%7}, {%8,%9}, {%0,%1,%2,%3};"
        : "+f"(c[0]), "+f"(c[1]), "+f"(c[2]), "+f"(c[3])
        : "r"(a[0]), "r"(a[1]), "r"(a[2]), "r"(a[3]), "r"(b[0]), "r"(b[1]));
}
// register-space split: float2 -> packed bf16x2 hi + bf16x2 lo
__device__ __forceinline__ void split2(float2 v, unsigned& hi, unsigned& lo) {
    unsigned h;
    asm("cvt.rn.bf16x2.f32 %0, %1, %2;" : "=r"(h) : "f"(v.y), "f"(v.x));
    float fx = __uint_as_float(h << 16);
    float fy = __uint_as_float(h & 0xffff0000u);
    unsigned l;
    asm("cvt.rn.bf16x2.f32 %0, %1, %2;" : "=r"(l) : "f"(v.y - fy), "f"(v.x - fx));
    hi = h;
    lo = l;
}

// ---------------------------------------------------------------------------
__global__ void reset_state() {
    if (threadIdx.x == 0) {
        g_cnt = 0;
        g_flag = 0;
    }
}

__global__ void copy_h(const float* __restrict__ hin) {
    int i = blockIdx.x * blockDim.x + threadIdx.x;
    for (; i < Bdim * Hdim; i += gridDim.x * blockDim.x) g_hbuf[0][i] = hin[i];
}

// split fp32 -> bf16 hi + bf16 lo (lo = round(v - hi))
__global__ void split_x(const float* __restrict__ src) {
    size_t i = (size_t)(blockIdx.x * blockDim.x + threadIdx.x) * 4;
    const size_t n = (size_t)Bdim * Sdim * Idim;
    for (; i < n; i += (size_t)gridDim.x * blockDim.x * 4) {
        float4 v = *reinterpret_cast<const float4*>(src + i);
        __nv_bfloat16 h0 = __float2bfloat16(v.x), h1 = __float2bfloat16(v.y);
        __nv_bfloat16 h2 = __float2bfloat16(v.z), h3 = __float2bfloat16(v.w);
        __nv_bfloat162 hi01{h0, h1}, hi23{h2, h3};
        __nv_bfloat162 lo01{__float2bfloat16(v.x - __bfloat162float(h0)),
                            __float2bfloat16(v.y - __bfloat162float(h1))};
        __nv_bfloat162 lo23{__float2bfloat16(v.z - __bfloat162float(h2)),
                            __float2bfloat16(v.w - __bfloat162float(h3))};
        *reinterpret_cast<__nv_bfloat162*>(&g_Xhi[i]) = hi01;
        *reinterpret_cast<__nv_bfloat162*>(&g_Xhi[i + 2]) = hi23;
        *reinterpret_cast<__nv_bfloat162*>(&g_Xlo[i]) = lo01;
        *reinterpret_cast<__nv_bfloat162*>(&g_Xlo[i + 2]) = lo23;
    }
}

__global__ void split_w(const float* __restrict__ src) {
    int i = blockIdx.x * blockDim.x + threadIdx.x;
    for (; i < Hdim * Idim; i += gridDim.x * blockDim.x) {
        float v = src[i];
        __nv_bfloat16 h = __float2bfloat16(v);
        g_Whi[i] = h;
        g_Wlo[i] = __float2bfloat16(v - __bfloat162float(h));
    }
}

__global__ void split_whh(const float* __restrict__ src) {
    int i = blockIdx.x * blockDim.x + threadIdx.x;
    for (; i < Hdim * Hdim; i += gridDim.x * blockDim.x) {
        float v = src[i];
        __nv_bfloat16 h = __float2bfloat16(v);
        g_Hhhi[i] = h;
        g_Hhlo[i] = __float2bfloat16(v - __bfloat162float(h));
    }
}

// ---------------------------------------------------------------------------
// Phase 1: wx = X @ Wih^T + b via bf16 tensor cores (unchanged from R8).
// ---------------------------------------------------------------------------
__global__ __launch_bounds__(256) void wx_gemm_tc(const float* __restrict__ bias,
                                                  float* __restrict__ out) {
    extern __shared__ __nv_bfloat16 smem_bf[];
    __nv_bfloat16* Ah = smem_bf;           // 2 bufs x 128 x 40
    __nv_bfloat16* Al = smem_bf + 10240;
    __nv_bfloat16* Bh = smem_bf + 20480;   // 2 bufs x 64 x 40
    __nv_bfloat16* Bl = smem_bf + 25600;

    const int tid = threadIdx.x;
    const int wid = tid >> 5, lane = tid & 31;
    const int g = lane >> 2, tg = lane & 3;
    const int warpM = (wid & 3) * 32;
    const int warpN = (wid >> 2) * 32;
    const long mBase = (long)blockIdx.y * 128;
    const int nBase = blockIdx.x * 64;

    const __nv_bfloat16* xh = g_Xhi + mBase * Idim;
    const __nv_bfloat16* xl = g_Xlo + mBase * Idim;
    const __nv_bfloat16* wh = g_Whi + (size_t)nBase * Idim;
    const __nv_bfloat16* wl = g_Wlo + (size_t)nBase * Idim;

    float acc[2][4][4];
#pragma unroll
    for (int i = 0; i < 2; i++)
#pragma unroll
        for (int j = 0; j < 4; j++)
#pragma unroll
            for (int r = 0; r < 4; r++) acc[i][j][r] = 0.f;

    const int ar0 = tid >> 2, aoff0 = (tid & 3) * 8;
    const int ar1 = (tid + 256) >> 2, aoff1 = ((tid + 256) & 3) * 8;
    const int br = tid >> 2, boff = (tid & 3) * 8;

#define LOAD_CHUNK(B, K0)                                                      \
    do {                                                                       \
        cp16(&Ah[(B) * 5120 + ar0 * 40 + aoff0], xh + ar0 * Idim + (K0) + aoff0); \
        cp16(&Ah[(B) * 5120 + ar1 * 40 + aoff1], xh + ar1 * Idim + (K0) + aoff1); \
        cp16(&Al[(B) * 5120 + ar0 * 40 + aoff0], xl + ar0 * Idim + (K0) + aoff0); \
        cp16(&Al[(B) * 5120 + ar1 * 40 + aoff1], xl + ar1 * Idim + (K0) + aoff1); \
        cp16(&Bh[(B) * 2560 + br * 40 + boff], wh + br * Idim + (K0) + boff);  \
        cp16(&Bl[(B) * 2560 + br * 40 + boff], wl + br * Idim + (K0) + boff);  \
    } while (0)

    LOAD_CHUNK(0, 0);
    CP_COMMIT();

    int buf = 0;
    for (int kt = 0; kt < Idim / 32; kt++) {
        if (kt + 1 < Idim / 32) LOAD_CHUNK(buf ^ 1, (kt + 1) * 32);
        CP_COMMIT();
        CP_WAIT(1);
        __syncthreads();

        const __nv_bfloat16* ah = Ah + buf * 5120;
        const __nv_bfloat16* al = Al + buf * 5120;
        const __nv_bfloat16* bh = Bh + buf * 2560;
        const __nv_bfloat16* bl = Bl + buf * 2560;

#pragma unroll
        for (int kk = 0; kk < 32; kk += 16) {
            unsigned afh[2][4], afl[2][4], bfh[4][2], bfl[4][2];
#pragma unroll
            for (int i = 0; i < 2; i++) {
                int r0 = (warpM + i * 16 + g) * 40 + kk + tg * 2;
                int r1 = r0 + 8 * 40;
                afh[i][0] = *reinterpret_cast<const unsigned*>(&ah[r0]);
                afh[i][1] = *reinterpret_cast<const unsigned*>(&ah[r1]);
                afh[i][2] = *reinterpret_cast<const unsigned*>(&ah[r0 + 8]);
                afh[i][3] = *reinterpret_cast<const unsigned*>(&ah[r1 + 8]);
                afl[i][0] = *reinterpret_cast<const unsigned*>(&al[r0]);
                afl[i][1] = *reinterpret_cast<const unsigned*>(&al[r1]);
                afl[i][2] = *reinterpret_cast<const unsigned*>(&al[r0 + 8]);
                afl[i][3] = *reinterpret_cast<const unsigned*>(&al[r1 + 8]);
            }
#pragma unroll
            for (int j = 0; j < 4; j++) {
                int r0 = (warpN + j * 8 + g) * 40 + kk + tg * 2;
                bfh[j][0] = *reinterpret_cast<const unsigned*>(&bh[r0]);
                bfh[j][1] = *reinterpret_cast<const unsigned*>(&bh[r0 + 8]);
                bfl[j][0] = *reinterpret_cast<const unsigned*>(&bl[r0]);
                bfl[j][1] = *reinterpret_cast<const unsigned*>(&bl[r0 + 8]);
            }
#pragma unroll
            for (int i = 0; i < 2; i++)
#pragma unroll
                for (int j = 0; j < 4; j++) {
                    mma_bf16(acc[i][j], afh[i], bfh[j]);
                    mma_bf16(acc[i][j], afh[i], bfl[j]);
                    mma_bf16(acc[i][j], afl[i], bfh[j]);
                }
        }
        __syncthreads();
        buf ^= 1;
    }

#pragma unroll
    for (int i = 0; i < 2; i++) {
        long row = mBase + warpM + i * 16 + g;
#pragma unroll
        for (int j = 0; j < 4; j++) {
            int col = nBase + warpN + j * 8 + tg * 2;
            float b0 = bias[col], b1 = bias[col + 1];
            float2 v0{acc[i][j][0] + b0, acc[i][j][1] + b1};
            float2 v1{acc[i][j][2] + b0, acc[i][j][3] + b1};
            *reinterpret_cast<float2*>(&out[row * Hdim + col]) = v0;
            *reinterpret_cast<float2*>(&out[(row + 8) * Hdim + col]) = v1;
        }
    }
}

// ---------------------------------------------------------------------------
// Phase 2: persistent recurrence — R6 publish/stage (fp32 h, 16x4KB bulk,
// release-atomic barrier) + HMMA compute with REGISTER-SPACE hi/lo split.
// 128 CTAs x 512 threads. CTA = 32 cols x 16 batches.
// Whh bf16 hi/lo slice (32x1024, pitch 1032) resident in smem all steps.
// 16 warps = K-slices of 64: per warp 4x k16 iters, A-frags built from fp32
// sH via float2 LDS.64 + cvt.rn.bf16x2 split; 12 HMMA per iter (3-product).
// ---------------------------------------------------------------------------
__global__ __launch_bounds__(REC_THREADS, 1)
void rnn_recur(const float* __restrict__ bhh, float* __restrict__ y,
               float* __restrict__ hlast) {
    extern __shared__ char smem_raw[];
    __nv_bfloat16* sWhi = reinterpret_cast<__nv_bfloat16*>(smem_raw);
    __nv_bfloat16* sWlo = reinterpret_cast<__nv_bfloat16*>(smem_raw + 66048);
    float* sH = reinterpret_cast<float*>(smem_raw + 132096);  // 16 x 1028 fp32
    float* sRed = sH;  // overlay: 16 x 640 (used after all sH reads)
    __shared__ unsigned long long mbar_storage;

    const int tid = threadIdx.x;
    const int bid = blockIdx.x;
    const int colBase = (bid & 31) * 32;
    const int batchBase = (bid >> 5) * 16;
    const unsigned mbar = (unsigned)__cvta_generic_to_shared(&mbar_storage);
    const unsigned sH_a = (unsigned)__cvta_generic_to_shared(sH);

    if (tid == 0) mbar_init(mbar, 1);

    // cache Whh hi/lo slice: 32 rows x 1024 bf16 = 4096 chunks of 16B each
#pragma unroll
    for (int i = 0; i < 8; i++) {
        int chunk = tid + i * REC_THREADS;
        int r = chunk >> 7, c = chunk & 127;
        *reinterpret_cast<float4*>(
            reinterpret_cast<char*>(sWhi) + r * 2064 + c * 16) =
            *reinterpret_cast<const float4*>(
                reinterpret_cast<const char*>(&g_Hhhi[(size_t)(colBase + r) << 10]) +
                c * 16);
        *reinterpret_cast<float4*>(
            reinterpret_cast<char*>(sWlo) + r * 2064 + c * 16) =
            *reinterpret_cast<const float4*>(
                reinterpret_cast<const char*>(&g_Hhlo[(size_t)(colBase + r) << 10]) +
                c * 16);
    }
    __syncthreads();  // mbar init + sW visible

    const int wid = tid >> 5, lane = tid & 31;
    const int g = lane >> 2, tg = lane & 3;
    const int kBase = wid * 64;

    const int ob = tid >> 5;  // batch 0..15
    const int oc = tid & 31;  // col 0..31
    const float bv = bhh[colBase + oc];
    const long ybase = (((long)(batchBase + ob)) << 20) + colBase + oc;
    const int hoff = ((batchBase + ob) << 10) + colBase + oc;
    const int rbase = ob * 40 + oc;
    float hv = 0.f;

    for (int s = 0; s < Sdim; s++) {
        const int p = s & 1;
        // stage fp32 h slice: 16 bulk copies of one 4KB row each
        if (tid == 0) {
            asm volatile("fence.proxy.async.shared::cta;" ::: "memory");
            mbar_expect_tx(mbar, 16 * 4096);
            const float* hsrc = g_hbuf[p] + ((long)batchBase << 10);
#pragma unroll
            for (int r = 0; r < 16; r++) {
                bulk_g2s(sH_a + (unsigned)(r * 1028 * 4), hsrc + (r << 10),
                         4096, mbar);
            }
        }
        float wxv = __ldg(&y[ybase + ((long)s << 10)]);  // overlap with copy
        mbar_wait(mbar, (unsigned)p);

        float acc[4][4];
#pragma unroll
        for (int j = 0; j < 4; j++)
#pragma unroll
            for (int r = 0; r < 4; r++) acc[j][r] = 0.f;

#pragma unroll
        for (int t = 0; t < 4; t++) {
            const int k = kBase + t * 16 + 2 * tg;
            // A fragments: load fp32 pairs, split to bf16 hi/lo in registers
            float2 v0 = *reinterpret_cast<const float2*>(&sH[g * 1028 + k]);
            float2 v1 = *reinterpret_cast<const float2*>(&sH[(g + 8) * 1028 + k]);
            float2 v2 = *reinterpret_cast<const float2*>(&sH[g * 1028 + k + 8]);
            float2 v3 = *reinterpret_cast<const float2*>(&sH[(g + 8) * 1028 + k + 8]);
            unsigned ah[4], al[4];
            split2(v0, ah[0], al[0]);
            split2(v1, ah[1], al[1]);
            split2(v2, ah[2], al[2]);
            split2(v3, ah[3], al[3]);
            const int kb = kBase + t * 16;
#pragma unroll
            for (int j = 0; j < 4; j++) {
                const int b0 = (8 * j + g) * PCH + kb + tg * 2;
                unsigned bh[2], bl[2];
                bh[0] = *reinterpret_cast<const unsigned*>(&sWhi[b0]);
                bh[1] = *reinterpret_cast<const unsigned*>(&sWhi[b0 + 8]);
                bl[0] = *reinterpret_cast<const unsigned*>(&sWlo[b0]);
                bl[1] = *reinterpret_cast<const unsigned*>(&sWlo[b0 + 8]);
                mma_bf16(acc[j], ah, bh);
                mma_bf16(acc[j], ah, bl);
                mma_bf16(acc[j], al, bh);
            }
        }
        __syncthreads();  // all sH reads done before sRed overlay writes

        // c0,c1 = (batch g, cols j*8+2tg..+1); c2,c3 = batch g+8
#pragma unroll
        for (int j = 0; j < 4; j++) {
            float2 w0{acc[j][0], acc[j][1]};
            float2 w1{acc[j][2], acc[j][3]};
            *reinterpret_cast<float2*>(
                &sRed[wid * 640 + g * 40 + j * 8 + tg * 2]) = w0;
            *reinterpret_cast<float2*>(
                &sRed[wid * 640 + (g + 8) * 40 + j * 8 + tg * 2]) = w1;
        }
        __syncthreads();

        float sum = 0.f;
#pragma unroll
        for (int w = 0; w < 16; w++) sum += sRed[w * 640 + rbase];

        hv = tanhf(wxv + sum + bv);
        g_hbuf[1 - p][hoff] = hv;         // single coalesced fp32 publish
        y[ybase + ((long)s << 10)] = hv;
        __syncthreads();  // CTA writes done before release
        if (tid == 0) {
            unsigned arrived = atom_add_release(&g_cnt, 1u) + 1u;
            unsigned step = (unsigned)(s + 1);
            if (arrived == step * (unsigned)NB_REC) st_release(&g_flag, step);
            while (ld_acquire(&g_flag) < step) {
            }
        }
        __syncthreads();
    }

    hlast[hoff] = hv;
}

// ---------------------------------------------------------------------------
extern "C" void kernel_launch(void* const* d_in, const int* in_sizes, int n_in,
                              void* d_out, int out_size) {
    const float* x = (const float*)d_in[0];      // [B,S,I]
    const float* h0 = (const float*)d_in[1];     // [B,H]
    const float* Wih_w = (const float*)d_in[2];  // [H,I]
    const float* Wih_b = (const float*)d_in[3];  // [H]
    const float* Whh_w = (const float*)d_in[4];  // [H,H]
    const float* Whh_b = (const float*)d_in[5];  // [H]
    float* y = (float*)d_out;                       // [B,S,H]
    float* hlast = y + (size_t)Bdim * Sdim * Hdim;  // [B,H]

    const int rec_smem = 66048 * 2 + 65792;  // W hi/lo + fp32 h = 197888
    cudaFuncSetAttribute(rnn_recur, cudaFuncAttributeMaxDynamicSharedMemorySize,
                         rec_smem);
    const int gemm_smem = 30720 * 2;  // 61440
    cudaFuncSetAttribute(wx_gemm_tc, cudaFuncAttributeMaxDynamicSharedMemorySize,
                         gemm_smem);

    reset_state<<<1, 32>>>();
    copy_h<<<64, 256>>>(h0);
    split_x<<<1024, 256>>>(x);
    split_w<<<256, 256>>>(Wih_w);
    split_whh<<<256, 256>>>(Whh_w);
    wx_gemm_tc<<<dim3(Hdim / 64, (Bdim * Sdim) / 128), 256, gemm_smem>>>(Wih_b, y);
    rnn_recur<<<NB_REC, REC_THREADS, rec_smem>>>(Whh_b, y, hlast);
}

// round 14
// speedup vs baseline: 1.4118x; 1.0180x over previous
#include <cuda_runtime.h>
#include <cuda_bf16.h>
#include <math.h>

#define Bdim 64
#define Sdim 1024
#define Idim 1024
#define Hdim 1024
#define NB_REC 128
#define REC_THREADS 512
#define PCH 1032  // bf16 smem row pitch: B-frag LDS banks (4g+tg)%32 distinct

// Scratch (allocation-free rule: __device__ globals)
__device__ float g_hbuf[2][Bdim * Hdim];  // fp32 h state, double-buffered
__device__ unsigned g_cnt4[4 * 32];       // per-batch-group barrier counters
__device__ unsigned g_flag4[4 * 32];      // per-batch-group release flags
// bf16 hi/lo split operands for tensor-core GEMMs
__device__ __nv_bfloat16 g_Xhi[(size_t)Bdim * Sdim * Idim];
__device__ __nv_bfloat16 g_Xlo[(size_t)Bdim * Sdim * Idim];
__device__ __nv_bfloat16 g_Whi[Hdim * Idim];
__device__ __nv_bfloat16 g_Wlo[Hdim * Idim];
__device__ __nv_bfloat16 g_Hhhi[Hdim * Hdim];
__device__ __nv_bfloat16 g_Hhlo[Hdim * Hdim];

// ---------------------------------------------------------------------------
__device__ __forceinline__ void cp16(void* d, const void* s) {
    unsigned sd = (unsigned)__cvta_generic_to_shared(d);
    asm volatile("cp.async.cg.shared.global [%0], [%1], 16;" :: "r"(sd), "l"(s));
}
#define CP_COMMIT() asm volatile("cp.async.commit_group;")
#define CP_WAIT(n) asm volatile("cp.async.wait_group %0;" :: "n"(n))

__device__ __forceinline__ unsigned atom_add_release(unsigned* p, unsigned v) {
    unsigned old;
    asm volatile("atom.add.release.gpu.u32 %0, [%1], %2;"
                 : "=r"(old) : "l"(p), "r"(v) : "memory");
    return old;
}
__device__ __forceinline__ void st_release(unsigned* p, unsigned v) {
    asm volatile("st.release.gpu.u32 [%0], %1;" :: "l"(p), "r"(v) : "memory");
}
__device__ __forceinline__ unsigned ld_acquire(const unsigned* p) {
    unsigned v;
    asm volatile("ld.acquire.gpu.u32 %0, [%1];" : "=r"(v) : "l"(p) : "memory");
    return v;
}
// bf16 mma: D(16x8,f32) += A(16x16,row) * B(16x8,col)
__device__ __forceinline__ void mma_bf16(float* c, const unsigned* a,
                                         const unsigned* b) {
    asm volatile(
        "mma.sync.aligned.m16n8k16.row.col.f32.bf16.bf16.f32 "
        "{%0,%1,%2,%3}, {%4,%5,%6,%7}, {%8,%9}, {%0,%1,%2,%3};"
        : "+f"(c[0]), "+f"(c[1]), "+f"(c[2]), "+f"(c[3])
        : "r"(a[0]), "r"(a[1]), "r"(a[2]), "r"(a[3]), "r"(b[0]), "r"(b[1]));
}
// register-space split: float2 -> packed bf16x2 hi + bf16x2 lo
__device__ __forceinline__ void split2(float2 v, unsigned& hi, unsigned& lo) {
    unsigned h;
    asm("cvt.rn.bf16x2.f32 %0, %1, %2;" : "=r"(h) : "f"(v.y), "f"(v.x));
    float fx = __uint_as_float(h << 16);
    float fy = __uint_as_float(h & 0xffff0000u);
    unsigned l;
    asm("cvt.rn.bf16x2.f32 %0, %1, %2;" : "=r"(l) : "f"(v.y - fy), "f"(v.x - fx));
    hi = h;
    lo = l;
}

// ---------------------------------------------------------------------------
__global__ void reset_state() {
    int i = threadIdx.x;
    if (i < 4 * 32) {
        g_cnt4[i] = 0;
        g_flag4[i] = 0;
    }
}

__global__ void copy_h(const float* __restrict__ hin) {
    int i = blockIdx.x * blockDim.x + threadIdx.x;
    for (; i < Bdim * Hdim; i += gridDim.x * blockDim.x) g_hbuf[0][i] = hin[i];
}

// split fp32 -> bf16 hi + bf16 lo (lo = round(v - hi))
__global__ void split_x(const float* __restrict__ src) {
    size_t i = (size_t)(blockIdx.x * blockDim.x + threadIdx.x) * 4;
    const size_t n = (size_t)Bdim * Sdim * Idim;
    for (; i < n; i += (size_t)gridDim.x * blockDim.x * 4) {
        float4 v = *reinterpret_cast<const float4*>(src + i);
        __nv_bfloat16 h0 = __float2bfloat16(v.x), h1 = __float2bfloat16(v.y);
        __nv_bfloat16 h2 = __float2bfloat16(v.z), h3 = __float2bfloat16(v.w);
        __nv_bfloat162 hi01{h0, h1}, hi23{h2, h3};
        __nv_bfloat162 lo01{__float2bfloat16(v.x - __bfloat162float(h0)),
                            __float2bfloat16(v.y - __bfloat162float(h1))};
        __nv_bfloat162 lo23{__float2bfloat16(v.z - __bfloat162float(h2)),
                            __float2bfloat16(v.w - __bfloat162float(h3))};
        *reinterpret_cast<__nv_bfloat162*>(&g_Xhi[i]) = hi01;
        *reinterpret_cast<__nv_bfloat162*>(&g_Xhi[i + 2]) = hi23;
        *reinterpret_cast<__nv_bfloat162*>(&g_Xlo[i]) = lo01;
        *reinterpret_cast<__nv_bfloat162*>(&g_Xlo[i + 2]) = lo23;
    }
}

__global__ void split_w(const float* __restrict__ src) {
    int i = blockIdx.x * blockDim.x + threadIdx.x;
    for (; i < Hdim * Idim; i += gridDim.x * blockDim.x) {
        float v = src[i];
        __nv_bfloat16 h = __float2bfloat16(v);
        g_Whi[i] = h;
        g_Wlo[i] = __float2bfloat16(v - __bfloat162float(h));
    }
}

__global__ void split_whh(const float* __restrict__ src) {
    int i = blockIdx.x * blockDim.x + threadIdx.x;
    for (; i < Hdim * Hdim; i += gridDim.x * blockDim.x) {
        float v = src[i];
        __nv_bfloat16 h = __float2bfloat16(v);
        g_Hhhi[i] = h;
        g_Hhlo[i] = __float2bfloat16(v - __bfloat162float(h));
    }
}

// ---------------------------------------------------------------------------
// Phase 1: wx = X @ Wih^T + b via bf16 tensor cores (unchanged from R8).
// ---------------------------------------------------------------------------
__global__ __launch_bounds__(256) void wx_gemm_tc(const float* __restrict__ bias,
                                                  float* __restrict__ out) {
    extern __shared__ __nv_bfloat16 smem_bf[];
    __nv_bfloat16* Ah = smem_bf;           // 2 bufs x 128 x 40
    __nv_bfloat16* Al = smem_bf + 10240;
    __nv_bfloat16* Bh = smem_bf + 20480;   // 2 bufs x 64 x 40
    __nv_bfloat16* Bl = smem_bf + 25600;

    const int tid = threadIdx.x;
    const int wid = tid >> 5, lane = tid & 31;
    const int g = lane >> 2, tg = lane & 3;
    const int warpM = (wid & 3) * 32;
    const int warpN = (wid >> 2) * 32;
    const long mBase = (long)blockIdx.y * 128;
    const int nBase = blockIdx.x * 64;

    const __nv_bfloat16* xh = g_Xhi + mBase * Idim;
    const __nv_bfloat16* xl = g_Xlo + mBase * Idim;
    const __nv_bfloat16* wh = g_Whi + (size_t)nBase * Idim;
    const __nv_bfloat16* wl = g_Wlo + (size_t)nBase * Idim;

    float acc[2][4][4];
#pragma unroll
    for (int i = 0; i < 2; i++)
#pragma unroll
        for (int j = 0; j < 4; j++)
#pragma unroll
            for (int r = 0; r < 4; r++) acc[i][j][r] = 0.f;

    const int ar0 = tid >> 2, aoff0 = (tid & 3) * 8;
    const int ar1 = (tid + 256) >> 2, aoff1 = ((tid + 256) & 3) * 8;
    const int br = tid >> 2, boff = (tid & 3) * 8;

#define LOAD_CHUNK(B, K0)                                                      \
    do {                                                                       \
        cp16(&Ah[(B) * 5120 + ar0 * 40 + aoff0], xh + ar0 * Idim + (K0) + aoff0); \
        cp16(&Ah[(B) * 5120 + ar1 * 40 + aoff1], xh + ar1 * Idim + (K0) + aoff1); \
        cp16(&Al[(B) * 5120 + ar0 * 40 + aoff0], xl + ar0 * Idim + (K0) + aoff0); \
        cp16(&Al[(B) * 5120 + ar1 * 40 + aoff1], xl + ar1 * Idim + (K0) + aoff1); \
        cp16(&Bh[(B) * 2560 + br * 40 + boff], wh + br * Idim + (K0) + boff);  \
        cp16(&Bl[(B) * 2560 + br * 40 + boff], wl + br * Idim + (K0) + boff);  \
    } while (0)

    LOAD_CHUNK(0, 0);
    CP_COMMIT();

    int buf = 0;
    for (int kt = 0; kt < Idim / 32; kt++) {
        if (kt + 1 < Idim / 32) LOAD_CHUNK(buf ^ 1, (kt + 1) * 32);
        CP_COMMIT();
        CP_WAIT(1);
        __syncthreads();

        const __nv_bfloat16* ah = Ah + buf * 5120;
        const __nv_bfloat16* al = Al + buf * 5120;
        const __nv_bfloat16* bh = Bh + buf * 2560;
        const __nv_bfloat16* bl = Bl + buf * 2560;

#pragma unroll
        for (int kk = 0; kk < 32; kk += 16) {
            unsigned afh[2][4], afl[2][4], bfh[4][2], bfl[4][2];
#pragma unroll
            for (int i = 0; i < 2; i++) {
                int r0 = (warpM + i * 16 + g) * 40 + kk + tg * 2;
                int r1 = r0 + 8 * 40;
                afh[i][0] = *reinterpret_cast<const unsigned*>(&ah[r0]);
                afh[i][1] = *reinterpret_cast<const unsigned*>(&ah[r1]);
                afh[i][2] = *reinterpret_cast<const unsigned*>(&ah[r0 + 8]);
                afh[i][3] = *reinterpret_cast<const unsigned*>(&ah[r1 + 8]);
                afl[i][0] = *reinterpret_cast<const unsigned*>(&al[r0]);
                afl[i][1] = *reinterpret_cast<const unsigned*>(&al[r1]);
                afl[i][2] = *reinterpret_cast<const unsigned*>(&al[r0 + 8]);
                afl[i][3] = *reinterpret_cast<const unsigned*>(&al[r1 + 8]);
            }
#pragma unroll
            for (int j = 0; j < 4; j++) {
                int r0 = (warpN + j * 8 + g) * 40 + kk + tg * 2;
                bfh[j][0] = *reinterpret_cast<const unsigned*>(&bh[r0]);
                bfh[j][1] = *reinterpret_cast<const unsigned*>(&bh[r0 + 8]);
                bfl[j][0] = *reinterpret_cast<const unsigned*>(&bl[r0]);
                bfl[j][1] = *reinterpret_cast<const unsigned*>(&bl[r0 + 8]);
            }
#pragma unroll
            for (int i = 0; i < 2; i++)
#pragma unroll
                for (int j = 0; j < 4; j++) {
                    mma_bf16(acc[i][j], afh[i], bfh[j]);
                    mma_bf16(acc[i][j], afh[i], bfl[j]);
                    mma_bf16(acc[i][j], afl[i], bfh[j]);
                }
        }
        __syncthreads();
        buf ^= 1;
    }

#pragma unroll
    for (int i = 0; i < 2; i++) {
        long row = mBase + warpM + i * 16 + g;
#pragma unroll
        for (int j = 0; j < 4; j++) {
            int col = nBase + warpN + j * 8 + tg * 2;
            float b0 = bias[col], b1 = bias[col + 1];
            float2 v0{acc[i][j][0] + b0, acc[i][j][1] + b1};
            float2 v1{acc[i][j][2] + b0, acc[i][j][3] + b1};
            *reinterpret_cast<float2*>(&out[row * Hdim + col]) = v0;
            *reinterpret_cast<float2*>(&out[(row + 8) * Hdim + col]) = v1;
        }
    }
}

// ---------------------------------------------------------------------------
// Phase 2: persistent recurrence, NO staging: HMMA A-frags loaded directly
// from L2 via __ldcg (h is a hot 256KB region; latency overlaps mma stream).
// 128 CTAs x 512 threads = 4 INDEPENDENT batch groups of 32 CTAs; barrier is
// per-group (batches never couple through Whh — only columns do).
// Whh bf16 hi/lo slice (32x1024, pitch 1032) resident in smem all steps.
// 16 warps = K-slices of 64: per warp 4x k16 iters, 12 HMMA each (3-product
// register-space hi/lo split). Partials reduced via dedicated sRed.
// ---------------------------------------------------------------------------
__global__ __launch_bounds__(REC_THREADS, 1)
void rnn_recur(const float* __restrict__ bhh, float* __restrict__ y,
               float* __restrict__ hlast) {
    extern __shared__ char smem_raw[];
    __nv_bfloat16* sWhi = reinterpret_cast<__nv_bfloat16*>(smem_raw);
    __nv_bfloat16* sWlo = reinterpret_cast<__nv_bfloat16*>(smem_raw + 66048);
    float* sRed = reinterpret_cast<float*>(smem_raw + 132096);  // 16 x 640

    const int tid = threadIdx.x;
    const int bid = blockIdx.x;
    const int colBase = (bid & 31) * 32;
    const int batchBase = (bid >> 5) * 16;
    const int grp = bid >> 5;

    // cache Whh hi/lo slice: 32 rows x 1024 bf16 = 4096 chunks of 16B each
#pragma unroll
    for (int i = 0; i < 8; i++) {
        int chunk = tid + i * REC_THREADS;
        int r = chunk >> 7, c = chunk & 127;
        *reinterpret_cast<float4*>(
            reinterpret_cast<char*>(sWhi) + r * 2064 + c * 16) =
            *reinterpret_cast<const float4*>(
                reinterpret_cast<const char*>(&g_Hhhi[(size_t)(colBase + r) << 10]) +
                c * 16);
        *reinterpret_cast<float4*>(
            reinterpret_cast<char*>(sWlo) + r * 2064 + c * 16) =
            *reinterpret_cast<const float4*>(
                reinterpret_cast<const char*>(&g_Hhlo[(size_t)(colBase + r) << 10]) +
                c * 16);
    }
    __syncthreads();

    const int lane = tid & 31;
    const int wid = tid >> 5;
    const int g = lane >> 2, tg = lane & 3;
    const int kBase = wid * 64;

    unsigned* cnt = &g_cnt4[grp * 32];
    unsigned* flag = &g_flag4[grp * 32];

    const int ob = tid >> 5;  // batch 0..15 (== wid)
    const int oc = tid & 31;  // col 0..31
    const float bv = bhh[colBase + oc];
    const long ybase = (((long)(batchBase + ob)) << 20) + colBase + oc;
    const int hoff = ((batchBase + ob) << 10) + colBase + oc;
    const int rbase = ob * 40 + oc;
    float hv = 0.f;

    for (int s = 0; s < Sdim; s++) {
        const int p = s & 1;
        float wxv = __ldg(&y[ybase + ((long)s << 10)]);
        const float* hsrc = g_hbuf[p] + ((long)batchBase << 10);

        float acc[4][4];
#pragma unroll
        for (int j = 0; j < 4; j++)
#pragma unroll
            for (int r = 0; r < 4; r++) acc[j][r] = 0.f;

#pragma unroll
        for (int t = 0; t < 4; t++) {
            const int k = kBase + t * 16 + 2 * tg;
            // A fragments straight from L2 (producers on other SMs -> ldcg)
            float2 v0 = __ldcg(reinterpret_cast<const float2*>(&hsrc[(g << 10) + k]));
            float2 v1 =
                __ldcg(reinterpret_cast<const float2*>(&hsrc[((g + 8) << 10) + k]));
            float2 v2 =
                __ldcg(reinterpret_cast<const float2*>(&hsrc[(g << 10) + k + 8]));
            float2 v3 = __ldcg(
                reinterpret_cast<const float2*>(&hsrc[((g + 8) << 10) + k + 8]));
            unsigned ah[4], al[4];
            split2(v0, ah[0], al[0]);
            split2(v1, ah[1], al[1]);
            split2(v2, ah[2], al[2]);
            split2(v3, ah[3], al[3]);
            const int kb = kBase + t * 16;
#pragma unroll
            for (int j = 0; j < 4; j++) {
                const int b0 = (8 * j + g) * PCH + kb + tg * 2;
                unsigned bh[2], bl[2];
                bh[0] = *reinterpret_cast<const unsigned*>(&sWhi[b0]);
                bh[1] = *reinterpret_cast<const unsigned*>(&sWhi[b0 + 8]);
                bl[0] = *reinterpret_cast<const unsigned*>(&sWlo[b0]);
                bl[1] = *reinterpret_cast<const unsigned*>(&sWlo[b0 + 8]);
                mma_bf16(acc[j], ah, bh);
                mma_bf16(acc[j], ah, bl);
                mma_bf16(acc[j], al, bh);
            }
        }

        // c0,c1 = (batch g, cols j*8+2tg..+1); c2,c3 = batch g+8
#pragma unroll
        for (int j = 0; j < 4; j++) {
            float2 w0{acc[j][0], acc[j][1]};
            float2 w1{acc[j][2], acc[j][3]};
            *reinterpret_cast<float2*>(
                &sRed[wid * 640 + g * 40 + j * 8 + tg * 2]) = w0;
            *reinterpret_cast<float2*>(
                &sRed[wid * 640 + (g + 8) * 40 + j * 8 + tg * 2]) = w1;
        }
        __syncthreads();

        float sum = 0.f;
#pragma unroll
        for (int w = 0; w < 16; w++) sum += sRed[w * 640 + rbase];

        hv = tanhf(wxv + sum + bv);
        g_hbuf[1 - p][hoff] = hv;         // publish h (group-visible via barrier)
        y[ybase + ((long)s << 10)] = hv;  // y output (own slot only)
        __syncthreads();  // CTA h-publish done before release; sRed reads done
        if (tid == 0) {
            unsigned arrived = atom_add_release(cnt, 1u) + 1u;
            unsigned step = (unsigned)(s + 1);
            if (arrived == step * 32u) st_release(flag, step);
            while (ld_acquire(flag) < step) {
            }
        }
        __syncthreads();
    }

    hlast[hoff] = hv;
}

// ---------------------------------------------------------------------------
extern "C" void kernel_launch(void* const* d_in, const int* in_sizes, int n_in,
                              void* d_out, int out_size) {
    const float* x = (const float*)d_in[0];      // [B,S,I]
    const float* h0 = (const float*)d_in[1];     // [B,H]
    const float* Wih_w = (const float*)d_in[2];  // [H,I]
    const float* Wih_b = (const float*)d_in[3];  // [H]
    const float* Whh_w = (const float*)d_in[4];  // [H,H]
    const float* Whh_b = (const float*)d_in[5];  // [H]
    float* y = (float*)d_out;                       // [B,S,H]
    float* hlast = y + (size_t)Bdim * Sdim * Hdim;  // [B,H]

    const int rec_smem = 66048 * 2 + 40960;  // W hi/lo + sRed = 173056
    cudaFuncSetAttribute(rnn_recur, cudaFuncAttributeMaxDynamicSharedMemorySize,
                         rec_smem);
    const int gemm_smem = 30720 * 2;  // 61440
    cudaFuncSetAttribute(wx_gemm_tc, cudaFuncAttributeMaxDynamicSharedMemorySize,
                         gemm_smem);

    reset_state<<<1, 128>>>();
    copy_h<<<64, 256>>>(h0);
    split_x<<<1024, 256>>>(x);
    split_w<<<256, 256>>>(Wih_w);
    split_whh<<<256, 256>>>(Whh_w);
    wx_gemm_tc<<<dim3(Hdim / 64, (Bdim * Sdim) / 128), 256, gemm_smem>>>(Wih_b, y);
    rnn_recur<<<NB_REC, REC_THREADS, rec_smem>>>(Whh_b, y, hlast);
}

// round 16
// speedup vs baseline: 1.5186x; 1.0756x over previous
#include <cuda_runtime.h>
#include <cuda_bf16.h>
#include <math.h>

#define Bdim 64
#define Sdim 1024
#define Idim 1024
#define Hdim 1024
#define NB_REC 128
#define REC_THREADS 512
#define PCH 1032  // bf16 smem row pitch: B-frag LDS banks (4g+tg)%32 distinct

// Scratch (allocation-free rule: __device__ globals)
__device__ float g_hbuf[2][Bdim * Hdim];  // fp32 h state, double-buffered
__device__ unsigned g_flagA[NB_REC * 32]; // per-CTA step flag, 128B stride
// bf16 hi/lo split operands for tensor-core GEMMs
__device__ __nv_bfloat16 g_Xhi[(size_t)Bdim * Sdim * Idim];
__device__ __nv_bfloat16 g_Xlo[(size_t)Bdim * Sdim * Idim];
__device__ __nv_bfloat16 g_Whi[Hdim * Idim];
__device__ __nv_bfloat16 g_Wlo[Hdim * Idim];
__device__ __nv_bfloat16 g_Hhhi[Hdim * Hdim];
__device__ __nv_bfloat16 g_Hhlo[Hdim * Hdim];

// ---------------------------------------------------------------------------
__device__ __forceinline__ void cp16(void* d, const void* s) {
    unsigned sd = (unsigned)__cvta_generic_to_shared(d);
    asm volatile("cp.async.cg.shared.global [%0], [%1], 16;" :: "r"(sd), "l"(s));
}
#define CP_COMMIT() asm volatile("cp.async.commit_group;")
#define CP_WAIT(n) asm volatile("cp.async.wait_group %0;" :: "n"(n))

__device__ __forceinline__ void st_release(unsigned* p, unsigned v) {
    asm volatile("st.release.gpu.u32 [%0], %1;" :: "l"(p), "r"(v) : "memory");
}
__device__ __forceinline__ unsigned ld_acquire(const unsigned* p) {
    unsigned v;
    asm volatile("ld.acquire.gpu.u32 %0, [%1];" : "=r"(v) : "l"(p) : "memory");
    return v;
}
// bf16 mma: D(16x8,f32) += A(16x16,row) * B(16x8,col)
__device__ __forceinline__ void mma_bf16(float* c, const unsigned* a,
                                         const unsigned* b) {
    asm volatile(
        "mma.sync.aligned.m16n8k16.row.col.f32.bf16.bf16.f32 "
        "{%0,%1,%2,%3}, {%4,%5,%6,%7}, {%8,%9}, {%0,%1,%2,%3};"
        : "+f"(c[0]), "+f"(c[1]), "+f"(c[2]), "+f"(c[3])
        : "r"(a[0]), "r"(a[1]), "r"(a[2]), "r"(a[3]), "r"(b[0]), "r"(b[1]));
}
// register-space split: float2 -> packed bf16x2 hi + bf16x2 lo
__device__ __forceinline__ void split2(float2 v, unsigned& hi, unsigned& lo) {
    unsigned h;
    asm("cvt.rn.bf16x2.f32 %0, %1, %2;" : "=r"(h) : "f"(v.y), "f"(v.x));
    float fx = __uint_as_float(h << 16);
    float fy = __uint_as_float(h & 0xffff0000u);
    unsigned l;
    asm("cvt.rn.bf16x2.f32 %0, %1, %2;" : "=r"(l) : "f"(v.y - fy), "f"(v.x - fx));
    hi = h;
    lo = l;
}

// ---------------------------------------------------------------------------
__global__ void reset_state() {
    int i = blockIdx.x * blockDim.x + threadIdx.x;
    for (; i < NB_REC * 32; i += gridDim.x * blockDim.x) g_flagA[i] = 0;
}

__global__ void copy_h(const float* __restrict__ hin) {
    int i = blockIdx.x * blockDim.x + threadIdx.x;
    for (; i < Bdim * Hdim; i += gridDim.x * blockDim.x) g_hbuf[0][i] = hin[i];
}

// split fp32 -> bf16 hi + bf16 lo (lo = round(v - hi))
__global__ void split_x(const float* __restrict__ src) {
    size_t i = (size_t)(blockIdx.x * blockDim.x + threadIdx.x) * 4;
    const size_t n = (size_t)Bdim * Sdim * Idim;
    for (; i < n; i += (size_t)gridDim.x * blockDim.x * 4) {
        float4 v = *reinterpret_cast<const float4*>(src + i);
        __nv_bfloat16 h0 = __float2bfloat16(v.x), h1 = __float2bfloat16(v.y);
        __nv_bfloat16 h2 = __float2bfloat16(v.z), h3 = __float2bfloat16(v.w);
        __nv_bfloat162 hi01{h0, h1}, hi23{h2, h3};
        __nv_bfloat162 lo01{__float2bfloat16(v.x - __bfloat162float(h0)),
                            __float2bfloat16(v.y - __bfloat162float(h1))};
        __nv_bfloat162 lo23{__float2bfloat16(v.z - __bfloat162float(h2)),
                            __float2bfloat16(v.w - __bfloat162float(h3))};
        *reinterpret_cast<__nv_bfloat162*>(&g_Xhi[i]) = hi01;
        *reinterpret_cast<__nv_bfloat162*>(&g_Xhi[i + 2]) = hi23;
        *reinterpret_cast<__nv_bfloat162*>(&g_Xlo[i]) = lo01;
        *reinterpret_cast<__nv_bfloat162*>(&g_Xlo[i + 2]) = lo23;
    }
}

__global__ void split_w(const float* __restrict__ src) {
    int i = blockIdx.x * blockDim.x + threadIdx.x;
    for (; i < Hdim * Idim; i += gridDim.x * blockDim.x) {
        float v = src[i];
        __nv_bfloat16 h = __float2bfloat16(v);
        g_Whi[i] = h;
        g_Wlo[i] = __float2bfloat16(v - __bfloat162float(h));
    }
}

__global__ void split_whh(const float* __restrict__ src) {
    int i = blockIdx.x * blockDim.x + threadIdx.x;
    for (; i < Hdim * Hdim; i += gridDim.x * blockDim.x) {
        float v = src[i];
        __nv_bfloat16 h = __float2bfloat16(v);
        g_Hhhi[i] = h;
        g_Hhlo[i] = __float2bfloat16(v - __bfloat162float(h));
    }
}

// ---------------------------------------------------------------------------
// Phase 1: wx = X @ Wih^T + b via bf16 tensor cores (unchanged from R8).
// ---------------------------------------------------------------------------
__global__ __launch_bounds__(256) void wx_gemm_tc(const float* __restrict__ bias,
                                                  float* __restrict__ out) {
    extern __shared__ __nv_bfloat16 smem_bf[];
    __nv_bfloat16* Ah = smem_bf;           // 2 bufs x 128 x 40
    __nv_bfloat16* Al = smem_bf + 10240;
    __nv_bfloat16* Bh = smem_bf + 20480;   // 2 bufs x 64 x 40
    __nv_bfloat16* Bl = smem_bf + 25600;

    const int tid = threadIdx.x;
    const int wid = tid >> 5, lane = tid & 31;
    const int g = lane >> 2, tg = lane & 3;
    const int warpM = (wid & 3) * 32;
    const int warpN = (wid >> 2) * 32;
    const long mBase = (long)blockIdx.y * 128;
    const int nBase = blockIdx.x * 64;

    const __nv_bfloat16* xh = g_Xhi + mBase * Idim;
    const __nv_bfloat16* xl = g_Xlo + mBase * Idim;
    const __nv_bfloat16* wh = g_Whi + (size_t)nBase * Idim;
    const __nv_bfloat16* wl = g_Wlo + (size_t)nBase * Idim;

    float acc[2][4][4];
#pragma unroll
    for (int i = 0; i < 2; i++)
#pragma unroll
        for (int j = 0; j < 4; j++)
#pragma unroll
            for (int r = 0; r < 4; r++) acc[i][j][r] = 0.f;

    const int ar0 = tid >> 2, aoff0 = (tid & 3) * 8;
    const int ar1 = (tid + 256) >> 2, aoff1 = ((tid + 256) & 3) * 8;
    const int br = tid >> 2, boff = (tid & 3) * 8;

#define LOAD_CHUNK(B, K0)                                                      \
    do {                                                                       \
        cp16(&Ah[(B) * 5120 + ar0 * 40 + aoff0], xh + ar0 * Idim + (K0) + aoff0); \
        cp16(&Ah[(B) * 5120 + ar1 * 40 + aoff1], xh + ar1 * Idim + (K0) + aoff1); \
        cp16(&Al[(B) * 5120 + ar0 * 40 + aoff0], xl + ar0 * Idim + (K0) + aoff0); \
        cp16(&Al[(B) * 5120 + ar1 * 40 + aoff1], xl + ar1 * Idim + (K0) + aoff1); \
        cp16(&Bh[(B) * 2560 + br * 40 + boff], wh + br * Idim + (K0) + boff);  \
        cp16(&Bl[(B) * 2560 + br * 40 + boff], wl + br * Idim + (K0) + boff);  \
    } while (0)

    LOAD_CHUNK(0, 0);
    CP_COMMIT();

    int buf = 0;
    for (int kt = 0; kt < Idim / 32; kt++) {
        if (kt + 1 < Idim / 32) LOAD_CHUNK(buf ^ 1, (kt + 1) * 32);
        CP_COMMIT();
        CP_WAIT(1);
        __syncthreads();

        const __nv_bfloat16* ah = Ah + buf * 5120;
        const __nv_bfloat16* al = Al + buf * 5120;
        const __nv_bfloat16* bh = Bh + buf * 2560;
        const __nv_bfloat16* bl = Bl + buf * 2560;

#pragma unroll
        for (int kk = 0; kk < 32; kk += 16) {
            unsigned afh[2][4], afl[2][4], bfh[4][2], bfl[4][2];
#pragma unroll
            for (int i = 0; i < 2; i++) {
                int r0 = (warpM + i * 16 + g) * 40 + kk + tg * 2;
                int r1 = r0 + 8 * 40;
                afh[i][0] = *reinterpret_cast<const unsigned*>(&ah[r0]);
                afh[i][1] = *reinterpret_cast<const unsigned*>(&ah[r1]);
                afh[i][2] = *reinterpret_cast<const unsigned*>(&ah[r0 + 8]);
                afh[i][3] = *reinterpret_cast<const unsigned*>(&ah[r1 + 8]);
                afl[i][0] = *reinterpret_cast<const unsigned*>(&al[r0]);
                afl[i][1] = *reinterpret_cast<const unsigned*>(&al[r1]);
                afl[i][2] = *reinterpret_cast<const unsigned*>(&al[r0 + 8]);
                afl[i][3] = *reinterpret_cast<const unsigned*>(&al[r1 + 8]);
            }
#pragma unroll
            for (int j = 0; j < 4; j++) {
                int r0 = (warpN + j * 8 + g) * 40 + kk + tg * 2;
                bfh[j][0] = *reinterpret_cast<const unsigned*>(&bh[r0]);
                bfh[j][1] = *reinterpret_cast<const unsigned*>(&bh[r0 + 8]);
                bfl[j][0] = *reinterpret_cast<const unsigned*>(&bl[r0]);
                bfl[j][1] = *reinterpret_cast<const unsigned*>(&bl[r0 + 8]);
            }
#pragma unroll
            for (int i = 0; i < 2; i++)
#pragma unroll
                for (int j = 0; j < 4; j++) {
                    mma_bf16(acc[i][j], afh[i], bfh[j]);
                    mma_bf16(acc[i][j], afh[i], bfl[j]);
                    mma_bf16(acc[i][j], afl[i], bfh[j]);
                }
        }
        __syncthreads();
        buf ^= 1;
    }

#pragma unroll
    for (int i = 0; i < 2; i++) {
        long row = mBase + warpM + i * 16 + g;
#pragma unroll
        for (int j = 0; j < 4; j++) {
            int col = nBase + warpN + j * 8 + tg * 2;
            float b0 = bias[col], b1 = bias[col + 1];
            float2 v0{acc[i][j][0] + b0, acc[i][j][1] + b1};
            float2 v1{acc[i][j][2] + b0, acc[i][j][3] + b1};
            *reinterpret_cast<float2*>(&out[row * Hdim + col]) = v0;
            *reinterpret_cast<float2*>(&out[(row + 8) * Hdim + col]) = v1;
        }
    }
}

// ---------------------------------------------------------------------------
// Phase 2: persistent recurrence. L2-direct A-frags (__ldcg), 4 independent
// 32-CTA batch groups. Barrier = contention-free per-CTA flag array:
// each CTA st.release's its own 128B-strided flag; warp 0's 32 lanes each
// ld.acquire-poll one group member's flag (parallel, no atomic serialization).
// wx prefetched one full step ahead (slot untouched until our own store).
// Whh bf16 hi/lo slice (32x1024, pitch 1032) resident in smem all steps.
// 16 warps = K-slices of 64: per warp 4x k16 iters, 12 HMMA each (3-product
// register-space hi/lo split). Partials reduced via dedicated sRed.
// ---------------------------------------------------------------------------
__global__ __launch_bounds__(REC_THREADS, 1)
void rnn_recur(const float* __restrict__ bhh, float* __restrict__ y,
               float* __restrict__ hlast) {
    extern __shared__ char smem_raw[];
    __nv_bfloat16* sWhi = reinterpret_cast<__nv_bfloat16*>(smem_raw);
    __nv_bfloat16* sWlo = reinterpret_cast<__nv_bfloat16*>(smem_raw + 66048);
    float* sRed = reinterpret_cast<float*>(smem_raw + 132096);  // 16 x 640

    const int tid = threadIdx.x;
    const int bid = blockIdx.x;
    const int colBase = (bid & 31) * 32;
    const int batchBase = (bid >> 5) * 16;

    // cache Whh hi/lo slice: 32 rows x 1024 bf16 = 4096 chunks of 16B each
#pragma unroll
    for (int i = 0; i < 8; i++) {
        int chunk = tid + i * REC_THREADS;
        int r = chunk >> 7, c = chunk & 127;
        *reinterpret_cast<float4*>(
            reinterpret_cast<char*>(sWhi) + r * 2064 + c * 16) =
            *reinterpret_cast<const float4*>(
                reinterpret_cast<const char*>(&g_Hhhi[(size_t)(colBase + r) << 10]) +
                c * 16);
        *reinterpret_cast<float4*>(
            reinterpret_cast<char*>(sWlo) + r * 2064 + c * 16) =
            *reinterpret_cast<const float4*>(
                reinterpret_cast<const char*>(&g_Hhlo[(size_t)(colBase + r) << 10]) +
                c * 16);
    }
    __syncthreads();

    const int lane = tid & 31;
    const int wid = tid >> 5;
    const int g = lane >> 2, tg = lane & 3;
    const int kBase = wid * 64;

    unsigned* myflag = &g_flagA[bid * 32];
    const unsigned* pollflag = &g_flagA[((bid & ~31) + lane) * 32];

    const int ob = tid >> 5;  // batch 0..15 (== wid)
    const int oc = tid & 31;  // col 0..31
    const float bv = bhh[colBase + oc];
    const long ybase = (((long)(batchBase + ob)) << 20) + colBase + oc;
    const int hoff = ((batchBase + ob) << 10) + colBase + oc;
    const int rbase = ob * 40 + oc;
    float hv = 0.f;

    float wxv_next = __ldg(&y[ybase]);  // wx for step 0
    for (int s = 0; s < Sdim; s++) {
        const int p = s & 1;
        const float wxv = wxv_next;
        if (s + 1 < Sdim)  // prefetch next step's wx (slot is ours alone)
            wxv_next = __ldg(&y[ybase + ((long)(s + 1) << 10)]);
        const float* hsrc = g_hbuf[p] + ((long)batchBase << 10);

        float acc[4][4];
#pragma unroll
        for (int j = 0; j < 4; j++)
#pragma unroll
            for (int r = 0; r < 4; r++) acc[j][r] = 0.f;

#pragma unroll
        for (int t = 0; t < 4; t++) {
            const int k = kBase + t * 16 + 2 * tg;
            // A fragments straight from L2 (producers on other SMs -> ldcg)
            float2 v0 = __ldcg(reinterpret_cast<const float2*>(&hsrc[(g << 10) + k]));
            float2 v1 =
                __ldcg(reinterpret_cast<const float2*>(&hsrc[((g + 8) << 10) + k]));
            float2 v2 =
                __ldcg(reinterpret_cast<const float2*>(&hsrc[(g << 10) + k + 8]));
            float2 v3 = __ldcg(
                reinterpret_cast<const float2*>(&hsrc[((g + 8) << 10) + k + 8]));
            unsigned ah[4], al[4];
            split2(v0, ah[0], al[0]);
            split2(v1, ah[1], al[1]);
            split2(v2, ah[2], al[2]);
            split2(v3, ah[3], al[3]);
            const int kb = kBase + t * 16;
#pragma unroll
            for (int j = 0; j < 4; j++) {
                const int b0 = (8 * j + g) * PCH + kb + tg * 2;
                unsigned bh[2], bl[2];
                bh[0] = *reinterpret_cast<const unsigned*>(&sWhi[b0]);
                bh[1] = *reinterpret_cast<const unsigned*>(&sWhi[b0 + 8]);
                bl[0] = *reinterpret_cast<const unsigned*>(&sWlo[b0]);
                bl[1] = *reinterpret_cast<const unsigned*>(&sWlo[b0 + 8]);
                mma_bf16(acc[j], ah, bh);
                mma_bf16(acc[j], ah, bl);
                mma_bf16(acc[j], al, bh);
            }
        }

        // c0,c1 = (batch g, cols j*8+2tg..+1); c2,c3 = batch g+8
#pragma unroll
        for (int j = 0; j < 4; j++) {
            float2 w0{acc[j][0], acc[j][1]};
            float2 w1{acc[j][2], acc[j][3]};
            *reinterpret_cast<float2*>(
                &sRed[wid * 640 + g * 40 + j * 8 + tg * 2]) = w0;
            *reinterpret_cast<float2*>(
                &sRed[wid * 640 + (g + 8) * 40 + j * 8 + tg * 2]) = w1;
        }
        __syncthreads();

        float sum = 0.f;
#pragma unroll
        for (int w = 0; w < 16; w++) sum += sRed[w * 640 + rbase];

        hv = tanhf(wxv + sum + bv);
        g_hbuf[1 - p][hoff] = hv;         // publish h (group-visible via barrier)
        y[ybase + ((long)s << 10)] = hv;  // y output (own slot only)
        __syncthreads();  // CTA h-publish + sRed reads done before release
        const unsigned step = (unsigned)(s + 1);
        if (tid == 0) st_release(myflag, step);
        if (tid < 32) {   // warp 0: 32 lanes poll the 32 group members
            while (ld_acquire(pollflag) < step) {
            }
        }
        __syncthreads();
    }

    hlast[hoff] = hv;
}

// ---------------------------------------------------------------------------
extern "C" void kernel_launch(void* const* d_in, const int* in_sizes, int n_in,
                              void* d_out, int out_size) {
    const float* x = (const float*)d_in[0];      // [B,S,I]
    const float* h0 = (const float*)d_in[1];     // [B,H]
    const float* Wih_w = (const float*)d_in[2];  // [H,I]
    const float* Wih_b = (const float*)d_in[3];  // [H]
    const float* Whh_w = (const float*)d_in[4];  // [H,H]
    const float* Whh_b = (const float*)d_in[5];  // [H]
    float* y = (float*)d_out;                       // [B,S,H]
    float* hlast = y + (size_t)Bdim * Sdim * Hdim;  // [B,H]

    const int rec_smem = 66048 * 2 + 40960;  // W hi/lo + sRed = 173056
    cudaFuncSetAttribute(rnn_recur, cudaFuncAttributeMaxDynamicSharedMemorySize,
                         rec_smem);
    const int gemm_smem = 30720 * 2;  // 61440
    cudaFuncSetAttribute(wx_gemm_tc, cudaFuncAttributeMaxDynamicSharedMemorySize,
                         gemm_smem);

    reset_state<<<16, 256>>>();
    copy_h<<<64, 256>>>(h0);
    split_x<<<1024, 256>>>(x);
    split_w<<<256, 256>>>(Wih_w);
    split_whh<<<256, 256>>>(Whh_w);
    wx_gemm_tc<<<dim3(Hdim / 64, (Bdim * Sdim) / 128), 256, gemm_smem>>>(Wih_b, y);
    rnn_recur<<<NB_REC, REC_THREADS, rec_smem>>>(Whh_b, y, hlast);
}